// round 4
// baseline (speedup 1.0000x reference)
#include <cuda_runtime.h>
#include <cstdint>

#define NN   100000
#define NE   1600000
#define CIN  128
#define CH1  128
#define CH2  64
#define HALF (NN/2)

// ---------------- scratch (static device globals; no allocs) ----------------
__device__ __align__(16) float g_xw1[(size_t)NN * CH1];   // x @ W1
__device__ __align__(16) float g_buf1[(size_t)NN * CH1];  // aggregated layer1 -> h1 (in place)
__device__ __align__(16) float g_xw2[(size_t)NN * CH2];   // h1 @ W2
__device__ __align__(16) float g_buf2[(size_t)NN * CH2];  // aggregated layer2
__device__ float g_dinv1[NN];               // deg accumulator -> rsqrt
__device__ float g_dinv2[NN];
__device__ int   g_src[NE];
__device__ int   g_dst[NE];
__device__ float g_c1e[NE];                 // per-edge norm coeff, layer 1
__device__ float g_c2e[NE];                 // per-edge norm coeff, layer 2

// vectorized global float4 reduction (sm_90+/sm_100+; ptxas accepts for sm_103a)
__device__ __forceinline__ void red_add_v4(float* addr, float a, float b, float c, float d) {
    asm volatile("red.global.add.v4.f32 [%0], {%1, %2, %3, %4};"
                 :: "l"(addr), "f"(a), "f"(b), "f"(c), "f"(d) : "memory");
}

// ---------------- degree / coeff prep ----------------
__global__ __launch_bounds__(256) void k_node_init() {
    int i = blockIdx.x * 256 + threadIdx.x;
    if (i < NN) { g_dinv1[i] = 1.0f; g_dinv2[i] = 1.0f; }  // self-loop weight
}

__global__ __launch_bounds__(256) void k_edges_pre(const int* __restrict__ ei,
                                                   const float* __restrict__ w,
                                                   const int* __restrict__ et) {
    int e = blockIdx.x * 256 + threadIdx.x;
    if (e >= NE) return;
    int s = ei[e];              // edge_index row 0 (src)
    int d = ei[NE + e];         // edge_index row 1 (dst)
    g_src[e] = s;
    g_dst[e] = d;
    atomicAdd(&g_dinv1[d], w[e]);
    atomicAdd(&g_dinv2[d], (float)et[e]);
}

__global__ __launch_bounds__(256) void k_rsqrt() {
    int i = blockIdx.x * 256 + threadIdx.x;
    if (i < NN) {
        g_dinv1[i] = rsqrtf(g_dinv1[i]);   // deg >= 1 always (self loop)
        g_dinv2[i] = rsqrtf(g_dinv2[i]);
    }
}

__global__ __launch_bounds__(256) void k_coeff(const float* __restrict__ w,
                                               const int* __restrict__ et) {
    int e = blockIdx.x * 256 + threadIdx.x;
    if (e >= NE) return;
    int s = g_src[e], d = g_dst[e];
    g_c1e[e] = g_dinv1[s] * w[e] * g_dinv1[d];
    g_c2e[e] = g_dinv2[s] * (float)et[e] * g_dinv2[d];
}

// ---------------- GEMM: Y[nrows,COUT] = X[nrows,CIN] @ W[CIN,COUT] ----------------
template<int COUT>
__global__ __launch_bounds__(128)
void k_gemm(const float* __restrict__ X, const float* __restrict__ W,
            float* __restrict__ Y, int nrows) {
    __shared__ float sX[64 * CIN];   // 32 KB
    int r0base = blockIdx.x * 64;
    int rows = nrows - r0base; if (rows > 64) rows = 64;   // tail = 32, multiple of 4
    for (int i = threadIdx.x; i < rows * CIN; i += 128)
        sX[i] = X[(size_t)r0base * CIN + i];
    __syncthreads();

    constexpr int CG = COUT / 4;            // float4 column groups
    int colq = threadIdx.x % CG;
    int rq   = threadIdx.x / CG;
    constexpr int RSTR = (128 / CG) * 4;    // row stride across r-quads
    const float4* W4 = (const float4*)W;

    for (int r0 = rq * 4; r0 + 3 < rows; r0 += RSTR) {
        float acc[4][4];
        #pragma unroll
        for (int j = 0; j < 4; j++)
            #pragma unroll
            for (int q = 0; q < 4; q++) acc[j][q] = 0.f;

        #pragma unroll 4
        for (int k = 0; k < CIN; ++k) {
            float4 wv = __ldg(&W4[k * CG + colq]);
            #pragma unroll
            for (int j = 0; j < 4; j++) {
                float xv = sX[(r0 + j) * CIN + k];
                acc[j][0] += xv * wv.x;
                acc[j][1] += xv * wv.y;
                acc[j][2] += xv * wv.z;
                acc[j][3] += xv * wv.w;
            }
        }
        #pragma unroll
        for (int j = 0; j < 4; j++) {
            float4 o = make_float4(acc[j][0], acc[j][1], acc[j][2], acc[j][3]);
            ((float4*)Y)[(size_t)(r0base + r0 + j) * CG + colq] = o;
        }
    }
}

// ---------------- self-loop init: out = xw * dinv^2 ----------------
template<int C>
__global__ __launch_bounds__(256)
void k_selfinit(const float* __restrict__ xw, const float* __restrict__ dinv,
                float* __restrict__ out) {
    int idx = blockIdx.x * 256 + threadIdx.x;           // float4 index
    constexpr int VPN = C / 4;
    if (idx >= NN * VPN) return;
    int node = idx / VPN;
    float dv = dinv[node];
    float sc = dv * dv;
    float4 v = ((const float4*)xw)[idx];
    v.x *= sc; v.y *= sc; v.z *= sc; v.w *= sc;
    ((float4*)out)[idx] = v;
}

// ---------------- edge scatter: out[dst] += xw[src] * coeff ----------------
template<int C>
__global__ __launch_bounds__(256)
void k_scatter(const float* __restrict__ xw, const float* __restrict__ cf,
               float* __restrict__ out) {
    constexpr int VPE = C / 4;
    int idx = blockIdx.x * 256 + threadIdx.x;
    int e  = idx / VPE;
    int ch = idx % VPE;
    if (e >= NE) return;
    float c = cf[e];
    if (c == 0.f) return;            // edge_type==0 edges contribute nothing
    int s = g_src[e], d = g_dst[e];
    float4 v = ((const float4*)xw)[(size_t)s * VPE + ch];
    red_add_v4(out + (size_t)d * C + (size_t)ch * 4,
               v.x * c, v.y * c, v.z * c, v.w * c);
}

// ---------------- bias + PReLU (in place) ----------------
__global__ __launch_bounds__(256)
void k_prelu1(float* __restrict__ buf, const float* __restrict__ b,
              const float* __restrict__ a) {
    int idx = blockIdx.x * 256 + threadIdx.x;
    if (idx >= NN * CH1) return;
    int c = idx & (CH1 - 1);
    float v = buf[idx] + b[c];
    buf[idx] = (v >= 0.f) ? v : a[c] * v;
}

// ---------------- final: prelu layer2 + half-split average ----------------
__global__ __launch_bounds__(256)
void k_final(const float* __restrict__ buf, const float* __restrict__ b,
             const float* __restrict__ a, float* __restrict__ out) {
    int i = blockIdx.x * 256 + threadIdx.x;
    if (i >= HALF * CH2) return;
    int c = i & (CH2 - 1);
    float v1 = buf[i] + b[c];
    v1 = (v1 >= 0.f) ? v1 : a[c] * v1;
    float v2 = buf[i + (size_t)HALF * CH2] + b[c];
    v2 = (v2 >= 0.f) ? v2 : a[c] * v2;
    out[i] = 0.5f * (v1 + v2);
}

// ---------------- launch ----------------
extern "C" void kernel_launch(void* const* d_in, const int* in_sizes, int n_in,
                              void* d_out, int out_size) {
    const float* x   = (const float*)d_in[0];
    const int*   ei  = (const int*)d_in[1];    // int32! (JAX x64 disabled)
    const float* ew  = (const float*)d_in[2];
    const int*   et  = (const int*)d_in[3];    // int32!
    const float* W1  = (const float*)d_in[4];
    const float* b1  = (const float*)d_in[5];
    const float* a1  = (const float*)d_in[6];
    const float* W2  = (const float*)d_in[7];
    const float* b2  = (const float*)d_in[8];
    const float* a2  = (const float*)d_in[9];
    float* out = (float*)d_out;

    float *xw1, *buf1, *xw2, *buf2, *dinv1, *dinv2, *c1e, *c2e;
    cudaGetSymbolAddress((void**)&xw1,  g_xw1);
    cudaGetSymbolAddress((void**)&buf1, g_buf1);
    cudaGetSymbolAddress((void**)&xw2,  g_xw2);
    cudaGetSymbolAddress((void**)&buf2, g_buf2);
    cudaGetSymbolAddress((void**)&dinv1, g_dinv1);
    cudaGetSymbolAddress((void**)&dinv2, g_dinv2);
    cudaGetSymbolAddress((void**)&c1e,  g_c1e);
    cudaGetSymbolAddress((void**)&c2e,  g_c2e);

    const int nodeGrid = (NN + 255) / 256;
    const int edgeGrid = (NE + 255) / 256;

    // degree + per-edge coefficients
    k_node_init<<<nodeGrid, 256>>>();
    k_edges_pre<<<edgeGrid, 256>>>(ei, ew, et);
    k_rsqrt<<<nodeGrid, 256>>>();
    k_coeff<<<edgeGrid, 256>>>(ew, et);

    // layer 1
    k_gemm<CH1><<<(NN + 63) / 64, 128>>>(x, W1, xw1, NN);
    k_selfinit<CH1><<<(NN * (CH1 / 4) + 255) / 256, 256>>>(xw1, dinv1, buf1);
    k_scatter<CH1><<<(NE * (CH1 / 4) + 255) / 256, 256>>>(xw1, c1e, buf1);
    k_prelu1<<<(NN * CH1 + 255) / 256, 256>>>(buf1, b1, a1);

    // layer 2
    k_gemm<CH2><<<(NN + 63) / 64, 128>>>(buf1, W2, xw2, NN);
    k_selfinit<CH2><<<(NN * (CH2 / 4) + 255) / 256, 256>>>(xw2, dinv2, buf2);
    k_scatter<CH2><<<(NE * (CH2 / 4) + 255) / 256, 256>>>(xw2, c2e, buf2);

    // epilogue
    k_final<<<(HALF * CH2 + 255) / 256, 256>>>(buf2, b2, a2, out);
}

// round 5
// speedup vs baseline: 1.2432x; 1.2432x over previous
#include <cuda_runtime.h>
#include <cstdint>

#define NN   100000
#define NE   1600000
#define CIN  128
#define CH1  128
#define CH2  64
#define HALF (NN/2)
#define NB1  ((NN + 255) / 256)     // 391 scan blocks

// ---------------- scratch (static device globals; no allocs) ----------------
__device__ __align__(16) float g_xw1[(size_t)NN * CH1];   // x @ W1
__device__ __align__(16) float g_buf1[(size_t)NN * CH1];  // h1 = prelu(agg1)
__device__ __align__(16) float g_xw2[(size_t)NN * CH2];   // h1 @ W2
__device__ __align__(16) float g_buf2[(size_t)NN * CH2];  // prelu(agg2)
__device__ float g_dinv1[NN];
__device__ float g_dinv2[NN];
__device__ int   g_cnt[NN];                 // per-dst edge count
__device__ int   g_rowptr[NN + 1];          // CSR row pointers
__device__ int   g_cursor[NN];              // fill cursors for reorder
__device__ int   g_psum[NB1];               // block partial sums for scan
__device__ __align__(16) int4 g_rec[NE];    // {src, c1_bits, c2_bits, 0} sorted by dst

// ---------------- f32x2 packed math helpers ----------------
__device__ __forceinline__ unsigned long long pack2(float x, float y) {
    unsigned long long r;
    asm("mov.b64 %0, {%1, %2};" : "=l"(r) : "f"(x), "f"(y));
    return r;
}
__device__ __forceinline__ void ffma2(unsigned long long& d,
                                      unsigned long long a, unsigned long long b) {
    asm("fma.rn.f32x2 %0, %1, %2, %3;" : "=l"(d) : "l"(a), "l"(b), "l"(d));
}
__device__ __forceinline__ float2 unpack2(unsigned long long v) {
    float2 f;
    asm("mov.b64 {%0, %1}, %2;" : "=f"(f.x), "=f"(f.y) : "l"(v));
    return f;
}

// ---------------- prep: init / histogram / rsqrt ----------------
__global__ __launch_bounds__(256) void k_init() {
    int i = blockIdx.x * 256 + threadIdx.x;
    if (i < NN) { g_cnt[i] = 0; g_dinv1[i] = 1.0f; g_dinv2[i] = 1.0f; }
}

__global__ __launch_bounds__(256) void k_pass1(const int* __restrict__ ei,
                                               const float* __restrict__ w,
                                               const int* __restrict__ et) {
    int e = blockIdx.x * 256 + threadIdx.x;
    if (e >= NE) return;
    int d = ei[NE + e];
    atomicAdd(&g_cnt[d], 1);
    atomicAdd(&g_dinv1[d], w[e]);
    atomicAdd(&g_dinv2[d], (float)et[e]);
}

__global__ __launch_bounds__(256) void k_rsqrt() {
    int i = blockIdx.x * 256 + threadIdx.x;
    if (i < NN) {
        g_dinv1[i] = rsqrtf(g_dinv1[i]);    // deg >= 1 (self loop)
        g_dinv2[i] = rsqrtf(g_dinv2[i]);
    }
}

// ---------------- 3-kernel exclusive scan of g_cnt -> g_rowptr ----------------
__global__ __launch_bounds__(256) void k_scan1() {
    __shared__ int s[256];
    int tid = threadIdx.x;
    int i = blockIdx.x * 256 + tid;
    int v = (i < NN) ? g_cnt[i] : 0;
    s[tid] = v;
    __syncthreads();
    for (int off = 1; off < 256; off <<= 1) {
        int t = (tid >= off) ? s[tid - off] : 0;
        __syncthreads();
        s[tid] += t;
        __syncthreads();
    }
    if (i < NN) g_rowptr[i] = s[tid] - v;   // block-local exclusive
    if (tid == 255) g_psum[blockIdx.x] = s[255];
}

__global__ __launch_bounds__(512) void k_scan2() {
    __shared__ int s[512];
    int tid = threadIdx.x;
    int v = (tid < NB1) ? g_psum[tid] : 0;
    s[tid] = v;
    __syncthreads();
    for (int off = 1; off < 512; off <<= 1) {
        int t = (tid >= off) ? s[tid - off] : 0;
        __syncthreads();
        s[tid] += t;
        __syncthreads();
    }
    if (tid < NB1) g_psum[tid] = s[tid] - v;   // exclusive over blocks
}

__global__ __launch_bounds__(256) void k_scan3() {
    int i = blockIdx.x * 256 + threadIdx.x;
    if (i < NN) {
        int r = g_rowptr[i] + g_psum[blockIdx.x];
        g_rowptr[i] = r;
        g_cursor[i] = r;
    }
    if (i == 0) g_rowptr[NN] = NE;
}

// ---------------- reorder edges into dst-sorted records ----------------
__global__ __launch_bounds__(256) void k_reorder(const int* __restrict__ ei,
                                                 const float* __restrict__ w,
                                                 const int* __restrict__ et) {
    int e = blockIdx.x * 256 + threadIdx.x;
    if (e >= NE) return;
    int s = ei[e];
    int d = ei[NE + e];
    int pos = atomicAdd(&g_cursor[d], 1);
    float c1 = g_dinv1[s] * w[e] * g_dinv1[d];
    float c2 = g_dinv2[s] * (float)et[e] * g_dinv2[d];
    g_rec[pos] = make_int4(s, __float_as_int(c1), __float_as_int(c2), 0);
}

// ---------------- GEMM: Y[nrows,COUT] = X[nrows,CIN] @ W[CIN,COUT] (f32x2) ----------------
template<int COUT>
__global__ __launch_bounds__(128)
void k_gemm(const float* __restrict__ X, const float* __restrict__ W,
            float* __restrict__ Y, int nrows) {
    __shared__ float sX[64 * CIN];   // 32 KB
    int r0base = blockIdx.x * 64;
    int rows = nrows - r0base; if (rows > 64) rows = 64;   // tail = 32, multiple of 4
    for (int i = threadIdx.x; i < rows * CIN; i += 128)
        sX[i] = X[(size_t)r0base * CIN + i];
    __syncthreads();

    constexpr int CG = COUT / 4;            // float4 column groups
    int colq = threadIdx.x % CG;
    int rq   = threadIdx.x / CG;
    constexpr int RSTR = (128 / CG) * 4;
    const float4* W4 = (const float4*)W;

    for (int r0 = rq * 4; r0 + 3 < rows; r0 += RSTR) {
        unsigned long long acc[4][2];
        #pragma unroll
        for (int j = 0; j < 4; j++) { acc[j][0] = pack2(0.f, 0.f); acc[j][1] = pack2(0.f, 0.f); }

        #pragma unroll 4
        for (int k = 0; k < CIN; ++k) {
            float4 wv = __ldg(&W4[k * CG + colq]);
            unsigned long long w01 = pack2(wv.x, wv.y);
            unsigned long long w23 = pack2(wv.z, wv.w);
            #pragma unroll
            for (int j = 0; j < 4; j++) {
                float xv = sX[(r0 + j) * CIN + k];
                unsigned long long xx = pack2(xv, xv);
                ffma2(acc[j][0], xx, w01);
                ffma2(acc[j][1], xx, w23);
            }
        }
        #pragma unroll
        for (int j = 0; j < 4; j++) {
            float2 p0 = unpack2(acc[j][0]);
            float2 p1 = unpack2(acc[j][1]);
            ((float4*)Y)[(size_t)(r0base + r0 + j) * CG + colq] =
                make_float4(p0.x, p0.y, p1.x, p1.y);
        }
    }
}

// ---------------- layer-1 aggregation: warp per dst, fused self+bias+prelu ----------------
// lane owns float4 (4 channels of 128)
__global__ __launch_bounds__(256)
void k_agg1(const float* __restrict__ xw, const float* __restrict__ b,
            const float* __restrict__ a, float* __restrict__ outbuf) {
    int warp = (blockIdx.x * 256 + threadIdx.x) >> 5;
    int lane = threadIdx.x & 31;
    if (warp >= NN) return;
    int dst = warp;

    const float4* xw4 = (const float4*)xw;
    float dv = g_dinv1[dst];
    float4 acc = xw4[(size_t)dst * 32 + lane];
    float sc = dv * dv;
    acc.x *= sc; acc.y *= sc; acc.z *= sc; acc.w *= sc;

    int start = g_rowptr[dst], end = g_rowptr[dst + 1];
    for (int base = start; base < end; base += 32) {
        int n = end - base; if (n > 32) n = 32;
        int4 rec = make_int4(0, 0, 0, 0);
        if (lane < n) rec = g_rec[base + lane];
        for (int j = 0; j < n; j++) {
            int   s = __shfl_sync(0xffffffffu, rec.x, j);
            float c = __int_as_float(__shfl_sync(0xffffffffu, rec.y, j));
            float4 v = xw4[(size_t)s * 32 + lane];
            acc.x += c * v.x; acc.y += c * v.y; acc.z += c * v.z; acc.w += c * v.w;
        }
    }

    // bias + prelu
    float4 bb = ((const float4*)b)[lane];
    float4 aa = ((const float4*)a)[lane];
    acc.x += bb.x; acc.y += bb.y; acc.z += bb.z; acc.w += bb.w;
    acc.x = (acc.x >= 0.f) ? acc.x : aa.x * acc.x;
    acc.y = (acc.y >= 0.f) ? acc.y : aa.y * acc.y;
    acc.z = (acc.z >= 0.f) ? acc.z : aa.z * acc.z;
    acc.w = (acc.w >= 0.f) ? acc.w : aa.w * acc.w;
    ((float4*)outbuf)[(size_t)dst * 32 + lane] = acc;
}

// ---------------- layer-2 aggregation: warp per dst, lane owns float2 (64 ch) ----------------
__global__ __launch_bounds__(256)
void k_agg2(const float* __restrict__ xw, const float* __restrict__ b,
            const float* __restrict__ a, float* __restrict__ outbuf) {
    int warp = (blockIdx.x * 256 + threadIdx.x) >> 5;
    int lane = threadIdx.x & 31;
    if (warp >= NN) return;
    int dst = warp;

    const float2* xw2 = (const float2*)xw;
    float dv = g_dinv2[dst];
    float2 acc = xw2[(size_t)dst * 32 + lane];
    float sc = dv * dv;
    acc.x *= sc; acc.y *= sc;

    int start = g_rowptr[dst], end = g_rowptr[dst + 1];
    for (int base = start; base < end; base += 32) {
        int n = end - base; if (n > 32) n = 32;
        int4 rec = make_int4(0, 0, 0, 0);
        if (lane < n) rec = g_rec[base + lane];
        for (int j = 0; j < n; j++) {
            float c = __int_as_float(__shfl_sync(0xffffffffu, rec.z, j));
            if (c == 0.f) continue;                       // edge_type==0 (warp-uniform)
            int s = __shfl_sync(0xffffffffu, rec.x, j);
            float2 v = xw2[(size_t)s * 32 + lane];
            acc.x += c * v.x; acc.y += c * v.y;
        }
    }

    float2 bb = ((const float2*)b)[lane];
    float2 aa = ((const float2*)a)[lane];
    acc.x += bb.x; acc.y += bb.y;
    acc.x = (acc.x >= 0.f) ? acc.x : aa.x * acc.x;
    acc.y = (acc.y >= 0.f) ? acc.y : aa.y * acc.y;
    ((float2*)outbuf)[(size_t)dst * 32 + lane] = acc;
}

// ---------------- final: half-split average ----------------
__global__ __launch_bounds__(256)
void k_final(const float* __restrict__ buf, float* __restrict__ out) {
    int i = blockIdx.x * 256 + threadIdx.x;          // float4 index
    if (i >= HALF * (CH2 / 4)) return;
    float4 v1 = ((const float4*)buf)[i];
    float4 v2 = ((const float4*)buf)[i + (size_t)HALF * (CH2 / 4)];
    float4 o = make_float4(0.5f * (v1.x + v2.x), 0.5f * (v1.y + v2.y),
                           0.5f * (v1.z + v2.z), 0.5f * (v1.w + v2.w));
    ((float4*)out)[i] = o;
}

// ---------------- launch ----------------
extern "C" void kernel_launch(void* const* d_in, const int* in_sizes, int n_in,
                              void* d_out, int out_size) {
    const float* x   = (const float*)d_in[0];
    const int*   ei  = (const int*)d_in[1];    // int32 (JAX x64 disabled)
    const float* ew  = (const float*)d_in[2];
    const int*   et  = (const int*)d_in[3];    // int32
    const float* W1  = (const float*)d_in[4];
    const float* b1  = (const float*)d_in[5];
    const float* a1  = (const float*)d_in[6];
    const float* W2  = (const float*)d_in[7];
    const float* b2  = (const float*)d_in[8];
    const float* a2  = (const float*)d_in[9];
    float* out = (float*)d_out;

    float *xw1, *buf1, *xw2, *buf2;
    cudaGetSymbolAddress((void**)&xw1,  g_xw1);
    cudaGetSymbolAddress((void**)&buf1, g_buf1);
    cudaGetSymbolAddress((void**)&xw2,  g_xw2);
    cudaGetSymbolAddress((void**)&buf2, g_buf2);

    const int nodeGrid = (NN + 255) / 256;
    const int edgeGrid = (NE + 255) / 256;
    const int aggGrid  = (NN + 7) / 8;            // 8 warps per 256-thread block

    // CSR build + norm coefficients
    k_init<<<nodeGrid, 256>>>();
    k_pass1<<<edgeGrid, 256>>>(ei, ew, et);
    k_rsqrt<<<nodeGrid, 256>>>();
    k_scan1<<<NB1, 256>>>();
    k_scan2<<<1, 512>>>();
    k_scan3<<<NB1, 256>>>();
    k_reorder<<<edgeGrid, 256>>>(ei, ew, et);

    // layer 1
    k_gemm<CH1><<<(NN + 63) / 64, 128>>>(x, W1, xw1, NN);
    k_agg1<<<aggGrid, 256>>>(xw1, b1, a1, buf1);

    // layer 2
    k_gemm<CH2><<<(NN + 63) / 64, 128>>>(buf1, W2, xw2, NN);
    k_agg2<<<aggGrid, 256>>>(xw2, b2, a2, buf2);

    // epilogue
    k_final<<<(HALF * (CH2 / 4) + 255) / 256, 256>>>(buf2, out);
}

// round 6
// speedup vs baseline: 1.2735x; 1.0244x over previous
#include <cuda_runtime.h>
#include <cstdint>

#define NN   100000
#define NE   1600000
#define CIN  128
#define CH1  128
#define CH2  64
#define HALF (NN/2)
#define NB1  ((NN + 255) / 256)     // 391 scan blocks

// ---------------- scratch (static device globals; no allocs) ----------------
__device__ __align__(16) float g_xw1[(size_t)NN * CH1];   // x @ W1
__device__ __align__(16) float g_buf1[(size_t)NN * CH1];  // h1 = prelu(agg1)
__device__ __align__(16) float g_xw2[(size_t)NN * CH2];   // h1 @ W2
__device__ __align__(16) float g_buf2[(size_t)NN * CH2];  // prelu(agg2)
__device__ float g_dinv1[NN];
__device__ float g_dinv2[NN];
__device__ int   g_cnt[NN];                 // per-dst edge count
__device__ int   g_rowptr[NN + 1];          // CSR row pointers
__device__ int   g_cursor[NN];              // fill cursors for reorder
__device__ int   g_psum[NB1];               // block partial sums for scan
__device__ __align__(8) int2 g_e1[NE];      // {src, c1_bits} sorted by dst
__device__ __align__(8) int2 g_e2[NE];      // {src, c2_bits} sorted by dst

// ---------------- f32x2 packed math helpers ----------------
__device__ __forceinline__ unsigned long long pack2(float x, float y) {
    unsigned long long r;
    asm("mov.b64 %0, {%1, %2};" : "=l"(r) : "f"(x), "f"(y));
    return r;
}
__device__ __forceinline__ void ffma2(unsigned long long& d,
                                      unsigned long long a, unsigned long long b) {
    asm("fma.rn.f32x2 %0, %1, %2, %3;" : "=l"(d) : "l"(a), "l"(b), "l"(d));
}
__device__ __forceinline__ float2 unpack2(unsigned long long v) {
    float2 f;
    asm("mov.b64 {%0, %1}, %2;" : "=f"(f.x), "=f"(f.y) : "l"(v));
    return f;
}

// ---------------- prep: init / histogram / rsqrt ----------------
__global__ __launch_bounds__(256) void k_init() {
    int i = blockIdx.x * 256 + threadIdx.x;
    if (i < NN) { g_cnt[i] = 0; g_dinv1[i] = 1.0f; g_dinv2[i] = 1.0f; }
}

__global__ __launch_bounds__(256) void k_pass1(const int* __restrict__ ei,
                                               const float* __restrict__ w,
                                               const int* __restrict__ et) {
    int e = blockIdx.x * 256 + threadIdx.x;
    if (e >= NE) return;
    int d = ei[NE + e];
    atomicAdd(&g_cnt[d], 1);
    atomicAdd(&g_dinv1[d], w[e]);
    atomicAdd(&g_dinv2[d], (float)et[e]);
}

__global__ __launch_bounds__(256) void k_rsqrt() {
    int i = blockIdx.x * 256 + threadIdx.x;
    if (i < NN) {
        g_dinv1[i] = rsqrtf(g_dinv1[i]);    // deg >= 1 (self loop)
        g_dinv2[i] = rsqrtf(g_dinv2[i]);
    }
}

// ---------------- 3-kernel exclusive scan of g_cnt -> g_rowptr ----------------
__global__ __launch_bounds__(256) void k_scan1() {
    __shared__ int s[256];
    int tid = threadIdx.x;
    int i = blockIdx.x * 256 + tid;
    int v = (i < NN) ? g_cnt[i] : 0;
    s[tid] = v;
    __syncthreads();
    for (int off = 1; off < 256; off <<= 1) {
        int t = (tid >= off) ? s[tid - off] : 0;
        __syncthreads();
        s[tid] += t;
        __syncthreads();
    }
    if (i < NN) g_rowptr[i] = s[tid] - v;   // block-local exclusive
    if (tid == 255) g_psum[blockIdx.x] = s[255];
}

__global__ __launch_bounds__(512) void k_scan2() {
    __shared__ int s[512];
    int tid = threadIdx.x;
    int v = (tid < NB1) ? g_psum[tid] : 0;
    s[tid] = v;
    __syncthreads();
    for (int off = 1; off < 512; off <<= 1) {
        int t = (tid >= off) ? s[tid - off] : 0;
        __syncthreads();
        s[tid] += t;
        __syncthreads();
    }
    if (tid < NB1) g_psum[tid] = s[tid] - v;   // exclusive over blocks
}

__global__ __launch_bounds__(256) void k_scan3() {
    int i = blockIdx.x * 256 + threadIdx.x;
    if (i < NN) {
        int r = g_rowptr[i] + g_psum[blockIdx.x];
        g_rowptr[i] = r;
        g_cursor[i] = r;
    }
    if (i == 0) g_rowptr[NN] = NE;
}

// ---------------- reorder edges into dst-sorted split records ----------------
__global__ __launch_bounds__(256) void k_reorder(const int* __restrict__ ei,
                                                 const float* __restrict__ w,
                                                 const int* __restrict__ et) {
    int e = blockIdx.x * 256 + threadIdx.x;
    if (e >= NE) return;
    int s = ei[e];
    int d = ei[NE + e];
    int pos = atomicAdd(&g_cursor[d], 1);
    float c1 = g_dinv1[s] * w[e] * g_dinv1[d];
    float c2 = g_dinv2[s] * (float)et[e] * g_dinv2[d];
    g_e1[pos] = make_int2(s, __float_as_int(c1));
    g_e2[pos] = make_int2(s, __float_as_int(c2));
}

// ---------------- GEMM: Y[nrows,COUT] = X[nrows,CIN] @ W[CIN,COUT] (f32x2) ----------------
template<int COUT>
__global__ __launch_bounds__(128)
void k_gemm(const float* __restrict__ X, const float* __restrict__ W,
            float* __restrict__ Y, int nrows) {
    __shared__ float sX[64 * CIN];   // 32 KB
    int r0base = blockIdx.x * 64;
    int rows = nrows - r0base; if (rows > 64) rows = 64;   // tail = 32, multiple of 4
    for (int i = threadIdx.x; i < rows * CIN; i += 128)
        sX[i] = X[(size_t)r0base * CIN + i];
    __syncthreads();

    constexpr int CG = COUT / 4;            // float4 column groups
    int colq = threadIdx.x % CG;
    int rq   = threadIdx.x / CG;
    constexpr int RSTR = (128 / CG) * 4;
    const float4* W4 = (const float4*)W;

    for (int r0 = rq * 4; r0 + 3 < rows; r0 += RSTR) {
        unsigned long long acc[4][2];
        #pragma unroll
        for (int j = 0; j < 4; j++) { acc[j][0] = pack2(0.f, 0.f); acc[j][1] = pack2(0.f, 0.f); }

        #pragma unroll 4
        for (int k = 0; k < CIN; ++k) {
            float4 wv = __ldg(&W4[k * CG + colq]);
            unsigned long long w01 = pack2(wv.x, wv.y);
            unsigned long long w23 = pack2(wv.z, wv.w);
            #pragma unroll
            for (int j = 0; j < 4; j++) {
                float xv = sX[(r0 + j) * CIN + k];
                unsigned long long xx = pack2(xv, xv);
                ffma2(acc[j][0], xx, w01);
                ffma2(acc[j][1], xx, w23);
            }
        }
        #pragma unroll
        for (int j = 0; j < 4; j++) {
            float2 p0 = unpack2(acc[j][0]);
            float2 p1 = unpack2(acc[j][1]);
            ((float4*)Y)[(size_t)(r0base + r0 + j) * CG + colq] =
                make_float4(p0.x, p0.y, p1.x, p1.y);
        }
    }
}

// ---------------- layer-1 aggregation: warp per dst, smem-staged records ----------------
// lane owns float4 (4 channels of 128)
__global__ __launch_bounds__(256)
void k_agg1(const float* __restrict__ xw, const float* __restrict__ b,
            const float* __restrict__ a, float* __restrict__ outbuf) {
    __shared__ int2 srec[8][32];
    int wq   = threadIdx.x >> 5;
    int lane = threadIdx.x & 31;
    int dst  = blockIdx.x * 8 + wq;
    if (dst >= NN) return;

    const float4* xw4 = (const float4*)xw;
    float dv = g_dinv1[dst];
    float4 acc = xw4[(size_t)dst * 32 + lane];
    float sc = dv * dv;
    acc.x *= sc; acc.y *= sc; acc.z *= sc; acc.w *= sc;

    int start = g_rowptr[dst], end = g_rowptr[dst + 1];
    for (int base = start; base < end; base += 32) {
        int n = end - base; if (n > 32) n = 32;
        if (lane < n) srec[wq][lane] = g_e1[base + lane];
        __syncwarp();
        int j = 0;
        for (; j + 4 <= n; j += 4) {
            int2 r0 = srec[wq][j], r1 = srec[wq][j + 1];
            int2 r2 = srec[wq][j + 2], r3 = srec[wq][j + 3];
            float4 v0 = xw4[(size_t)r0.x * 32 + lane];
            float4 v1 = xw4[(size_t)r1.x * 32 + lane];
            float4 v2 = xw4[(size_t)r2.x * 32 + lane];
            float4 v3 = xw4[(size_t)r3.x * 32 + lane];
            float c0 = __int_as_float(r0.y), c1 = __int_as_float(r1.y);
            float c2 = __int_as_float(r2.y), c3 = __int_as_float(r3.y);
            acc.x += c0 * v0.x; acc.y += c0 * v0.y; acc.z += c0 * v0.z; acc.w += c0 * v0.w;
            acc.x += c1 * v1.x; acc.y += c1 * v1.y; acc.z += c1 * v1.z; acc.w += c1 * v1.w;
            acc.x += c2 * v2.x; acc.y += c2 * v2.y; acc.z += c2 * v2.z; acc.w += c2 * v2.w;
            acc.x += c3 * v3.x; acc.y += c3 * v3.y; acc.z += c3 * v3.z; acc.w += c3 * v3.w;
        }
        for (; j < n; j++) {
            int2 r = srec[wq][j];
            float c = __int_as_float(r.y);
            float4 v = xw4[(size_t)r.x * 32 + lane];
            acc.x += c * v.x; acc.y += c * v.y; acc.z += c * v.z; acc.w += c * v.w;
        }
        __syncwarp();
    }

    float4 bb = ((const float4*)b)[lane];
    float4 aa = ((const float4*)a)[lane];
    acc.x += bb.x; acc.y += bb.y; acc.z += bb.z; acc.w += bb.w;
    acc.x = (acc.x >= 0.f) ? acc.x : aa.x * acc.x;
    acc.y = (acc.y >= 0.f) ? acc.y : aa.y * acc.y;
    acc.z = (acc.z >= 0.f) ? acc.z : aa.z * acc.z;
    acc.w = (acc.w >= 0.f) ? acc.w : aa.w * acc.w;
    ((float4*)outbuf)[(size_t)dst * 32 + lane] = acc;
}

// ---------------- layer-2 aggregation: warp per dst, lane owns float2 (64 ch) ----------------
__global__ __launch_bounds__(256)
void k_agg2(const float* __restrict__ xw, const float* __restrict__ b,
            const float* __restrict__ a, float* __restrict__ outbuf) {
    __shared__ int2 srec[8][32];
    int wq   = threadIdx.x >> 5;
    int lane = threadIdx.x & 31;
    int dst  = blockIdx.x * 8 + wq;
    if (dst >= NN) return;

    const float2* xw2 = (const float2*)xw;
    float dv = g_dinv2[dst];
    float2 acc = xw2[(size_t)dst * 32 + lane];
    float sc = dv * dv;
    acc.x *= sc; acc.y *= sc;

    int start = g_rowptr[dst], end = g_rowptr[dst + 1];
    for (int base = start; base < end; base += 32) {
        int n = end - base; if (n > 32) n = 32;
        if (lane < n) srec[wq][lane] = g_e2[base + lane];
        __syncwarp();
        int j = 0;
        for (; j + 4 <= n; j += 4) {
            int2 r0 = srec[wq][j], r1 = srec[wq][j + 1];
            int2 r2 = srec[wq][j + 2], r3 = srec[wq][j + 3];
            float c0 = __int_as_float(r0.y), c1 = __int_as_float(r1.y);
            float c2 = __int_as_float(r2.y), c3 = __int_as_float(r3.y);
            if (c0 != 0.f) { float2 v = xw2[(size_t)r0.x * 32 + lane]; acc.x += c0 * v.x; acc.y += c0 * v.y; }
            if (c1 != 0.f) { float2 v = xw2[(size_t)r1.x * 32 + lane]; acc.x += c1 * v.x; acc.y += c1 * v.y; }
            if (c2 != 0.f) { float2 v = xw2[(size_t)r2.x * 32 + lane]; acc.x += c2 * v.x; acc.y += c2 * v.y; }
            if (c3 != 0.f) { float2 v = xw2[(size_t)r3.x * 32 + lane]; acc.x += c3 * v.x; acc.y += c3 * v.y; }
        }
        for (; j < n; j++) {
            int2 r = srec[wq][j];
            float c = __int_as_float(r.y);
            if (c != 0.f) { float2 v = xw2[(size_t)r.x * 32 + lane]; acc.x += c * v.x; acc.y += c * v.y; }
        }
        __syncwarp();
    }

    float2 bb = ((const float2*)b)[lane];
    float2 aa = ((const float2*)a)[lane];
    acc.x += bb.x; acc.y += bb.y;
    acc.x = (acc.x >= 0.f) ? acc.x : aa.x * acc.x;
    acc.y = (acc.y >= 0.f) ? acc.y : aa.y * acc.y;
    ((float2*)outbuf)[(size_t)dst * 32 + lane] = acc;
}

// ---------------- final: half-split average ----------------
__global__ __launch_bounds__(256)
void k_final(const float* __restrict__ buf, float* __restrict__ out) {
    int i = blockIdx.x * 256 + threadIdx.x;          // float4 index
    if (i >= HALF * (CH2 / 4)) return;
    float4 v1 = ((const float4*)buf)[i];
    float4 v2 = ((const float4*)buf)[i + (size_t)HALF * (CH2 / 4)];
    float4 o = make_float4(0.5f * (v1.x + v2.x), 0.5f * (v1.y + v2.y),
                           0.5f * (v1.z + v2.z), 0.5f * (v1.w + v2.w));
    ((float4*)out)[i] = o;
}

// ---------------- launch ----------------
extern "C" void kernel_launch(void* const* d_in, const int* in_sizes, int n_in,
                              void* d_out, int out_size) {
    const float* x   = (const float*)d_in[0];
    const int*   ei  = (const int*)d_in[1];    // int32 (JAX x64 disabled)
    const float* ew  = (const float*)d_in[2];
    const int*   et  = (const int*)d_in[3];    // int32
    const float* W1  = (const float*)d_in[4];
    const float* b1  = (const float*)d_in[5];
    const float* a1  = (const float*)d_in[6];
    const float* W2  = (const float*)d_in[7];
    const float* b2  = (const float*)d_in[8];
    const float* a2  = (const float*)d_in[9];
    float* out = (float*)d_out;

    float *xw1, *buf1, *xw2, *buf2;
    cudaGetSymbolAddress((void**)&xw1,  g_xw1);
    cudaGetSymbolAddress((void**)&buf1, g_buf1);
    cudaGetSymbolAddress((void**)&xw2,  g_xw2);
    cudaGetSymbolAddress((void**)&buf2, g_buf2);

    const int nodeGrid = (NN + 255) / 256;
    const int edgeGrid = (NE + 255) / 256;
    const int aggGrid  = (NN + 7) / 8;            // 8 warps per 256-thread block

    // CSR build + norm coefficients
    k_init<<<nodeGrid, 256>>>();
    k_pass1<<<edgeGrid, 256>>>(ei, ew, et);
    k_rsqrt<<<nodeGrid, 256>>>();
    k_scan1<<<NB1, 256>>>();
    k_scan2<<<1, 512>>>();
    k_scan3<<<NB1, 256>>>();
    k_reorder<<<edgeGrid, 256>>>(ei, ew, et);

    // layer 1
    k_gemm<CH1><<<(NN + 63) / 64, 128>>>(x, W1, xw1, NN);
    k_agg1<<<aggGrid, 256>>>(xw1, b1, a1, buf1);

    // layer 2
    k_gemm<CH2><<<(NN + 63) / 64, 128>>>(buf1, W2, xw2, NN);
    k_agg2<<<aggGrid, 256>>>(xw2, b2, a2, buf2);

    // epilogue
    k_final<<<(HALF * (CH2 / 4) + 255) / 256, 256>>>(buf2, out);
}

// round 8
// speedup vs baseline: 1.7173x; 1.3485x over previous
#include <cuda_runtime.h>
#include <cstdint>

#define NN   100000
#define NE   1600000
#define CIN  128
#define CH1  128
#define CH2  64
#define HALF (NN/2)
#define NB1  ((NN + 255) / 256)     // 391 scan blocks

// ---------------- scratch (static device globals; no allocs) ----------------
__device__ __align__(16) float g_xw1[(size_t)NN * CH1];   // x @ W1
__device__ __align__(16) float g_buf1[(size_t)NN * CH1];  // h1 = prelu(agg1)
__device__ __align__(16) float g_xw2[(size_t)NN * CH2];   // h1 @ W2
__device__ __align__(16) float g_buf2[(size_t)NN * CH2];  // prelu(agg2)
__device__ float g_dinv1[NN];
__device__ float g_dinv2[NN];
__device__ int   g_cnt[NN];                 // per-dst edge count
__device__ int   g_rowptr[NN + 1];          // CSR row pointers
__device__ int   g_cursor[NN];              // fill cursors for reorder
__device__ int   g_psum[NB1];               // block partial sums for scan
__device__ __align__(8) int2 g_e1[NE];      // {src, c1_bits} sorted by dst
__device__ __align__(8) int2 g_e2[NE];      // {src, c2_bits} sorted by dst

// ---------------- f32x2 packed math helpers ----------------
__device__ __forceinline__ unsigned long long pack2(float x, float y) {
    unsigned long long r;
    asm("mov.b64 %0, {%1, %2};" : "=l"(r) : "f"(x), "f"(y));
    return r;
}
__device__ __forceinline__ void ffma2(unsigned long long& d,
                                      unsigned long long a, unsigned long long b) {
    asm("fma.rn.f32x2 %0, %1, %2, %3;" : "=l"(d) : "l"(a), "l"(b), "l"(d));
}
__device__ __forceinline__ float2 unpack2(unsigned long long v) {
    float2 f;
    asm("mov.b64 {%0, %1}, %2;" : "=f"(f.x), "=f"(f.y) : "l"(v));
    return f;
}

// ---------------- prep: init / histogram ----------------
__global__ __launch_bounds__(256) void k_init() {
    int i = blockIdx.x * 256 + threadIdx.x;
    if (i < NN) { g_cnt[i] = 0; g_dinv1[i] = 1.0f; g_dinv2[i] = 1.0f; }
}

__global__ __launch_bounds__(256) void k_pass1(const int* __restrict__ ei,
                                               const float* __restrict__ w,
                                               const int* __restrict__ et) {
    int e = blockIdx.x * 256 + threadIdx.x;
    if (e >= NE) return;
    int d = ei[NE + e];
    atomicAdd(&g_cnt[d], 1);
    atomicAdd(&g_dinv1[d], w[e]);
    atomicAdd(&g_dinv2[d], (float)et[e]);
}

// ---------------- 3-kernel exclusive scan of g_cnt -> g_rowptr ----------------
__global__ __launch_bounds__(256) void k_scan1() {
    __shared__ int s[256];
    int tid = threadIdx.x;
    int i = blockIdx.x * 256 + tid;
    int v = (i < NN) ? g_cnt[i] : 0;
    s[tid] = v;
    __syncthreads();
    for (int off = 1; off < 256; off <<= 1) {
        int t = (tid >= off) ? s[tid - off] : 0;
        __syncthreads();
        s[tid] += t;
        __syncthreads();
    }
    if (i < NN) g_rowptr[i] = s[tid] - v;   // block-local exclusive
    if (tid == 255) g_psum[blockIdx.x] = s[255];
}

__global__ __launch_bounds__(512) void k_scan2() {
    __shared__ int s[512];
    int tid = threadIdx.x;
    int v = (tid < NB1) ? g_psum[tid] : 0;
    s[tid] = v;
    __syncthreads();
    for (int off = 1; off < 512; off <<= 1) {
        int t = (tid >= off) ? s[tid - off] : 0;
        __syncthreads();
        s[tid] += t;
        __syncthreads();
    }
    if (tid < NB1) g_psum[tid] = s[tid] - v;   // exclusive over blocks
}

__global__ __launch_bounds__(256) void k_scan3() {      // + fused rsqrt
    int i = blockIdx.x * 256 + threadIdx.x;
    if (i < NN) {
        int r = g_rowptr[i] + g_psum[blockIdx.x];
        g_rowptr[i] = r;
        g_cursor[i] = r;
        g_dinv1[i] = rsqrtf(g_dinv1[i]);    // deg >= 1 (self loop)
        g_dinv2[i] = rsqrtf(g_dinv2[i]);
    }
    if (i == 0) g_rowptr[NN] = NE;
}

// ---------------- reorder edges into dst-sorted split records ----------------
__global__ __launch_bounds__(256) void k_reorder(const int* __restrict__ ei,
                                                 const float* __restrict__ w,
                                                 const int* __restrict__ et) {
    int e = blockIdx.x * 256 + threadIdx.x;
    if (e >= NE) return;
    int s = ei[e];
    int d = ei[NE + e];
    int pos = atomicAdd(&g_cursor[d], 1);
    float c1 = g_dinv1[s] * w[e] * g_dinv1[d];
    float c2 = g_dinv2[s] * (float)et[e] * g_dinv2[d];
    g_e1[pos] = make_int2(s, __float_as_int(c1));
    g_e2[pos] = make_int2(s, __float_as_int(c2));
}

// ---------------- GEMM: Y[nrows,COUT] = X[nrows,CIN] @ W[CIN,COUT] ----------------
// 256 threads, per-thread 8x8 output tile, f32x2 column-pair accumulators.
// W pairs load directly as LDS.128 (no packing); only x broadcast needs a mov.
template<int COUT>
__global__ __launch_bounds__(256)
void k_gemm(const float* __restrict__ X, const float* __restrict__ W,
            float* __restrict__ Y, int nrows) {
    constexpr int TC = 8, TR = 8, KC = 32;
    constexpr int CG = COUT / TC;         // col groups: 16 (128) or 8 (64)
    constexpr int RG = 256 / CG;          // row groups: 16 or 32
    constexpr int RT = RG * TR;           // rows/block tile: 128 or 256
    __shared__ float sX[RT][KC];          // 16/32 KB
    __shared__ float sW[KC][COUT];        // 16/8  KB

    int tid = threadIdx.x;
    int tx = tid % CG, ty = tid / CG;
    int r0base = blockIdx.x * RT;
    int r0 = ty * TR;

    unsigned long long acc[TR][4];
    #pragma unroll
    for (int j = 0; j < TR; j++) {
        acc[j][0] = 0ULL; acc[j][1] = 0ULL; acc[j][2] = 0ULL; acc[j][3] = 0ULL;
    }

    for (int k0 = 0; k0 < CIN; k0 += KC) {
        // stage X chunk (rows of this tile, zero-padded past nrows)
        #pragma unroll
        for (int idx = tid; idx < RT * (KC / 4); idx += 256) {
            int row = idx / (KC / 4);
            int kq  = idx % (KC / 4);
            int grow = r0base + row;
            float4 v = (grow < nrows)
                ? ((const float4*)(X + (size_t)grow * CIN + k0))[kq]
                : make_float4(0.f, 0.f, 0.f, 0.f);
            *(float4*)&sX[row][kq * 4] = v;
        }
        // stage W chunk
        #pragma unroll
        for (int idx = tid; idx < KC * (COUT / 4); idx += 256) {
            int kk = idx / (COUT / 4);
            int cq = idx % (COUT / 4);
            *(float4*)&sW[kk][cq * 4] = ((const float4*)(W + (size_t)(k0 + kk) * COUT))[cq];
        }
        __syncthreads();

        #pragma unroll 4
        for (int kk = 0; kk < KC; kk++) {
            ulonglong2 w01 = *(const ulonglong2*)&sW[kk][tx * TC];
            ulonglong2 w23 = *(const ulonglong2*)&sW[kk][tx * TC + 4];
            #pragma unroll
            for (int j = 0; j < TR; j++) {
                float xv = sX[r0 + j][kk];
                unsigned long long xx = pack2(xv, xv);
                ffma2(acc[j][0], xx, w01.x);
                ffma2(acc[j][1], xx, w01.y);
                ffma2(acc[j][2], xx, w23.x);
                ffma2(acc[j][3], xx, w23.y);
            }
        }
        __syncthreads();
    }

    #pragma unroll
    for (int j = 0; j < TR; j++) {
        int grow = r0base + r0 + j;
        if (grow < nrows) {
            float2 p0 = unpack2(acc[j][0]);
            float2 p1 = unpack2(acc[j][1]);
            float2 p2 = unpack2(acc[j][2]);
            float2 p3 = unpack2(acc[j][3]);
            float4* yp = (float4*)(Y + (size_t)grow * COUT + tx * TC);
            yp[0] = make_float4(p0.x, p0.y, p1.x, p1.y);
            yp[1] = make_float4(p2.x, p2.y, p3.x, p3.y);
        }
    }
}

// ---------------- layer-1 aggregation: warp per dst, smem-staged records ----------------
__global__ __launch_bounds__(256)
void k_agg1(const float* __restrict__ xw, const float* __restrict__ b,
            const float* __restrict__ a, float* __restrict__ outbuf) {
    __shared__ int2 srec[8][32];
    int wq   = threadIdx.x >> 5;
    int lane = threadIdx.x & 31;
    int dst  = blockIdx.x * 8 + wq;
    if (dst >= NN) return;

    const float4* xw4 = (const float4*)xw;
    float dv = g_dinv1[dst];
    float4 acc = xw4[(size_t)dst * 32 + lane];
    float sc = dv * dv;
    acc.x *= sc; acc.y *= sc; acc.z *= sc; acc.w *= sc;

    int start = g_rowptr[dst], end = g_rowptr[dst + 1];
    for (int base = start; base < end; base += 32) {
        int n = end - base; if (n > 32) n = 32;
        if (lane < n) srec[wq][lane] = g_e1[base + lane];
        __syncwarp();
        int j = 0;
        for (; j + 4 <= n; j += 4) {
            int2 r0 = srec[wq][j], r1 = srec[wq][j + 1];
            int2 r2 = srec[wq][j + 2], r3 = srec[wq][j + 3];
            float4 v0 = xw4[(size_t)r0.x * 32 + lane];
            float4 v1 = xw4[(size_t)r1.x * 32 + lane];
            float4 v2 = xw4[(size_t)r2.x * 32 + lane];
            float4 v3 = xw4[(size_t)r3.x * 32 + lane];
            float c0 = __int_as_float(r0.y), c1 = __int_as_float(r1.y);
            float c2 = __int_as_float(r2.y), c3 = __int_as_float(r3.y);
            acc.x += c0 * v0.x; acc.y += c0 * v0.y; acc.z += c0 * v0.z; acc.w += c0 * v0.w;
            acc.x += c1 * v1.x; acc.y += c1 * v1.y; acc.z += c1 * v1.z; acc.w += c1 * v1.w;
            acc.x += c2 * v2.x; acc.y += c2 * v2.y; acc.z += c2 * v2.z; acc.w += c2 * v2.w;
            acc.x += c3 * v3.x; acc.y += c3 * v3.y; acc.z += c3 * v3.z; acc.w += c3 * v3.w;
        }
        for (; j < n; j++) {
            int2 r = srec[wq][j];
            float c = __int_as_float(r.y);
            float4 v = xw4[(size_t)r.x * 32 + lane];
            acc.x += c * v.x; acc.y += c * v.y; acc.z += c * v.z; acc.w += c * v.w;
        }
        __syncwarp();
    }

    float4 bb = ((const float4*)b)[lane];
    float4 aa = ((const float4*)a)[lane];
    acc.x += bb.x; acc.y += bb.y; acc.z += bb.z; acc.w += bb.w;
    acc.x = (acc.x >= 0.f) ? acc.x : aa.x * acc.x;
    acc.y = (acc.y >= 0.f) ? acc.y : aa.y * acc.y;
    acc.z = (acc.z >= 0.f) ? acc.z : aa.z * acc.z;
    acc.w = (acc.w >= 0.f) ? acc.w : aa.w * acc.w;
    ((float4*)outbuf)[(size_t)dst * 32 + lane] = acc;
}

// ---------------- layer-2 aggregation: warp per dst, lane owns float2 (64 ch) ----------------
__global__ __launch_bounds__(256)
void k_agg2(const float* __restrict__ xw, const float* __restrict__ b,
            const float* __restrict__ a, float* __restrict__ outbuf) {
    __shared__ int2 srec[8][32];
    int wq   = threadIdx.x >> 5;
    int lane = threadIdx.x & 31;
    int dst  = blockIdx.x * 8 + wq;
    if (dst >= NN) return;

    const float2* xw2 = (const float2*)xw;
    float dv = g_dinv2[dst];
    float2 acc = xw2[(size_t)dst * 32 + lane];
    float sc = dv * dv;
    acc.x *= sc; acc.y *= sc;

    int start = g_rowptr[dst], end = g_rowptr[dst + 1];
    for (int base = start; base < end; base += 32) {
        int n = end - base; if (n > 32) n = 32;
        if (lane < n) srec[wq][lane] = g_e2[base + lane];
        __syncwarp();
        int j = 0;
        for (; j + 4 <= n; j += 4) {
            int2 r0 = srec[wq][j], r1 = srec[wq][j + 1];
            int2 r2 = srec[wq][j + 2], r3 = srec[wq][j + 3];
            float c0 = __int_as_float(r0.y), c1 = __int_as_float(r1.y);
            float c2 = __int_as_float(r2.y), c3 = __int_as_float(r3.y);
            if (c0 != 0.f) { float2 v = xw2[(size_t)r0.x * 32 + lane]; acc.x += c0 * v.x; acc.y += c0 * v.y; }
            if (c1 != 0.f) { float2 v = xw2[(size_t)r1.x * 32 + lane]; acc.x += c1 * v.x; acc.y += c1 * v.y; }
            if (c2 != 0.f) { float2 v = xw2[(size_t)r2.x * 32 + lane]; acc.x += c2 * v.x; acc.y += c2 * v.y; }
            if (c3 != 0.f) { float2 v = xw2[(size_t)r3.x * 32 + lane]; acc.x += c3 * v.x; acc.y += c3 * v.y; }
        }
        for (; j < n; j++) {
            int2 r = srec[wq][j];
            float c = __int_as_float(r.y);
            if (c != 0.f) { float2 v = xw2[(size_t)r.x * 32 + lane]; acc.x += c * v.x; acc.y += c * v.y; }
        }
        __syncwarp();
    }

    float2 bb = ((const float2*)b)[lane];
    float2 aa = ((const float2*)a)[lane];
    acc.x += bb.x; acc.y += bb.y;
    acc.x = (acc.x >= 0.f) ? acc.x : aa.x * acc.x;
    acc.y = (acc.y >= 0.f) ? acc.y : aa.y * acc.y;
    ((float2*)outbuf)[(size_t)dst * 32 + lane] = acc;
}

// ---------------- final: half-split average ----------------
__global__ __launch_bounds__(256)
void k_final(const float* __restrict__ buf, float* __restrict__ out) {
    int i = blockIdx.x * 256 + threadIdx.x;          // float4 index
    if (i >= HALF * (CH2 / 4)) return;
    float4 v1 = ((const float4*)buf)[i];
    float4 v2 = ((const float4*)buf)[i + (size_t)HALF * (CH2 / 4)];
    float4 o = make_float4(0.5f * (v1.x + v2.x), 0.5f * (v1.y + v2.y),
                           0.5f * (v1.z + v2.z), 0.5f * (v1.w + v2.w));
    ((float4*)out)[i] = o;
}

// ---------------- launch ----------------
extern "C" void kernel_launch(void* const* d_in, const int* in_sizes, int n_in,
                              void* d_out, int out_size) {
    const float* x   = (const float*)d_in[0];
    const int*   ei  = (const int*)d_in[1];    // int32 (JAX x64 disabled)
    const float* ew  = (const float*)d_in[2];
    const int*   et  = (const int*)d_in[3];    // int32
    const float* W1  = (const float*)d_in[4];
    const float* b1  = (const float*)d_in[5];
    const float* a1  = (const float*)d_in[6];
    const float* W2  = (const float*)d_in[7];
    const float* b2  = (const float*)d_in[8];
    const float* a2  = (const float*)d_in[9];
    float* out = (float*)d_out;

    float *xw1, *buf1, *xw2, *buf2;
    cudaGetSymbolAddress((void**)&xw1,  g_xw1);
    cudaGetSymbolAddress((void**)&buf1, g_buf1);
    cudaGetSymbolAddress((void**)&xw2,  g_xw2);
    cudaGetSymbolAddress((void**)&buf2, g_buf2);

    const int nodeGrid = (NN + 255) / 256;
    const int edgeGrid = (NE + 255) / 256;
    const int aggGrid  = (NN + 7) / 8;            // 8 warps per 256-thread block

    // CSR build + norm coefficients
    k_init<<<nodeGrid, 256>>>();
    k_pass1<<<edgeGrid, 256>>>(ei, ew, et);
    k_scan1<<<NB1, 256>>>();
    k_scan2<<<1, 512>>>();
    k_scan3<<<NB1, 256>>>();
    k_reorder<<<edgeGrid, 256>>>(ei, ew, et);

    // layer 1  (tile rows = 128 for COUT=128)
    k_gemm<CH1><<<(NN + 127) / 128, 256>>>(x, W1, xw1, NN);
    k_agg1<<<aggGrid, 256>>>(xw1, b1, a1, buf1);

    // layer 2  (tile rows = 256 for COUT=64)
    k_gemm<CH2><<<(NN + 255) / 256, 256>>>(buf1, W2, xw2, NN);
    k_agg2<<<aggGrid, 256>>>(xw2, b2, a2, buf2);

    // epilogue
    k_final<<<(HALF * (CH2 / 4) + 255) / 256, 256>>>(buf2, out);
}

// round 12
// speedup vs baseline: 1.8043x; 1.0507x over previous
#include <cuda_runtime.h>
#include <cstdint>

#define NN   100000
#define NE   1600000
#define CIN  128
#define CH1  128
#define CH2  64
#define HALF (NN/2)
#define NB1  ((NN + 255) / 256)     // 391 scan blocks

// ---------------- scratch (static device globals; no allocs) ----------------
__device__ __align__(16) float g_xw1[(size_t)NN * CH1];   // x @ W1
__device__ __align__(16) float g_buf1[(size_t)NN * CH1];  // h1 = prelu(agg1)
__device__ __align__(16) float g_xw2[(size_t)NN * CH2];   // h1 @ W2
__device__ __align__(16) float g_buf2[(size_t)NN * CH2];  // prelu(agg2)
__device__ float g_dinv1[NN];
__device__ float g_dinv2[NN];
__device__ int   g_cnt[NN];                 // per-dst edge count
__device__ int   g_rowptr[NN + 1];          // CSR row pointers
__device__ int   g_cursor[NN];              // fill cursors for reorder
__device__ int   g_psum[NB1];               // block partial sums for scan
__device__ __align__(8) int2 g_e1[NE];      // {src, c1_bits} sorted by dst
__device__ __align__(8) int2 g_e2[NE];      // {src, c2_bits} sorted by dst

// ---------------- side stream + events: lazily created on first call ----------
// (host-side resources only; no device allocations; created during the
//  harness's correctness call, long before graph capture; the GPU work
//  launched by kernel_launch is identical on every call)
static cudaStream_t g_s2     = nullptr;
static cudaEvent_t  g_evFork = nullptr;
static cudaEvent_t  g_evJoin = nullptr;

// ---------------- f32x2 packed math helpers ----------------
__device__ __forceinline__ unsigned long long pack2(float x, float y) {
    unsigned long long r;
    asm("mov.b64 %0, {%1, %2};" : "=l"(r) : "f"(x), "f"(y));
    return r;
}
__device__ __forceinline__ void ffma2(unsigned long long& d,
                                      unsigned long long a, unsigned long long b) {
    asm("fma.rn.f32x2 %0, %1, %2, %3;" : "=l"(d) : "l"(a), "l"(b), "l"(d));
}
__device__ __forceinline__ float2 unpack2(unsigned long long v) {
    float2 f;
    asm("mov.b64 {%0, %1}, %2;" : "=f"(f.x), "=f"(f.y) : "l"(v));
    return f;
}

// ---------------- prep: init / histogram ----------------
__global__ __launch_bounds__(256) void k_init() {
    int i = blockIdx.x * 256 + threadIdx.x;
    if (i < NN) { g_cnt[i] = 0; g_dinv1[i] = 1.0f; g_dinv2[i] = 1.0f; }
}

__global__ __launch_bounds__(256) void k_pass1(const int* __restrict__ ei,
                                               const float* __restrict__ w,
                                               const int* __restrict__ et) {
    int e = blockIdx.x * 256 + threadIdx.x;
    if (e >= NE) return;
    int d = ei[NE + e];
    atomicAdd(&g_cnt[d], 1);
    atomicAdd(&g_dinv1[d], w[e]);
    atomicAdd(&g_dinv2[d], (float)et[e]);
}

// ---------------- 3-kernel exclusive scan of g_cnt -> g_rowptr ----------------
__global__ __launch_bounds__(256) void k_scan1() {
    __shared__ int s[256];
    int tid = threadIdx.x;
    int i = blockIdx.x * 256 + tid;
    int v = (i < NN) ? g_cnt[i] : 0;
    s[tid] = v;
    __syncthreads();
    for (int off = 1; off < 256; off <<= 1) {
        int t = (tid >= off) ? s[tid - off] : 0;
        __syncthreads();
        s[tid] += t;
        __syncthreads();
    }
    if (i < NN) g_rowptr[i] = s[tid] - v;   // block-local exclusive
    if (tid == 255) g_psum[blockIdx.x] = s[255];
}

__global__ __launch_bounds__(512) void k_scan2() {
    __shared__ int s[512];
    int tid = threadIdx.x;
    int v = (tid < NB1) ? g_psum[tid] : 0;
    s[tid] = v;
    __syncthreads();
    for (int off = 1; off < 512; off <<= 1) {
        int t = (tid >= off) ? s[tid - off] : 0;
        __syncthreads();
        s[tid] += t;
        __syncthreads();
    }
    if (tid < NB1) g_psum[tid] = s[tid] - v;   // exclusive over blocks
}

__global__ __launch_bounds__(256) void k_scan3() {      // + fused rsqrt
    int i = blockIdx.x * 256 + threadIdx.x;
    if (i < NN) {
        int r = g_rowptr[i] + g_psum[blockIdx.x];
        g_rowptr[i] = r;
        g_cursor[i] = r;
        g_dinv1[i] = rsqrtf(g_dinv1[i]);    // deg >= 1 (self loop)
        g_dinv2[i] = rsqrtf(g_dinv2[i]);
    }
    if (i == 0) g_rowptr[NN] = NE;
}

// ---------------- reorder edges into dst-sorted split records ----------------
__global__ __launch_bounds__(256) void k_reorder(const int* __restrict__ ei,
                                                 const float* __restrict__ w,
                                                 const int* __restrict__ et) {
    int e = blockIdx.x * 256 + threadIdx.x;
    if (e >= NE) return;
    int s = ei[e];
    int d = ei[NE + e];
    int pos = atomicAdd(&g_cursor[d], 1);
    float c1 = g_dinv1[s] * w[e] * g_dinv1[d];
    float c2 = g_dinv2[s] * (float)et[e] * g_dinv2[d];
    g_e1[pos] = make_int2(s, __float_as_int(c1));
    g_e2[pos] = make_int2(s, __float_as_int(c2));
}

// ---------------- GEMM: Y[nrows,COUT] = X[nrows,CIN] @ W[CIN,COUT] ----------------
// 256 threads, per-thread 8x8 output tile, f32x2 column-pair accumulators.
template<int COUT>
__global__ __launch_bounds__(256)
void k_gemm(const float* __restrict__ X, const float* __restrict__ W,
            float* __restrict__ Y, int nrows) {
    constexpr int TC = 8, TR = 8, KC = 32;
    constexpr int CG = COUT / TC;         // col groups: 16 (128) or 8 (64)
    constexpr int RG = 256 / CG;          // row groups: 16 or 32
    constexpr int RT = RG * TR;           // rows/block tile: 128 or 256
    __shared__ float sX[RT][KC];          // 16/32 KB
    __shared__ float sW[KC][COUT];        // 16/8  KB

    int tid = threadIdx.x;
    int tx = tid % CG, ty = tid / CG;
    int r0base = blockIdx.x * RT;
    int r0 = ty * TR;

    unsigned long long acc[TR][4];
    #pragma unroll
    for (int j = 0; j < TR; j++) {
        acc[j][0] = 0ULL; acc[j][1] = 0ULL; acc[j][2] = 0ULL; acc[j][3] = 0ULL;
    }

    for (int k0 = 0; k0 < CIN; k0 += KC) {
        #pragma unroll
        for (int idx = tid; idx < RT * (KC / 4); idx += 256) {
            int row = idx / (KC / 4);
            int kq  = idx % (KC / 4);
            int grow = r0base + row;
            float4 v = (grow < nrows)
                ? ((const float4*)(X + (size_t)grow * CIN + k0))[kq]
                : make_float4(0.f, 0.f, 0.f, 0.f);
            *(float4*)&sX[row][kq * 4] = v;
        }
        #pragma unroll
        for (int idx = tid; idx < KC * (COUT / 4); idx += 256) {
            int kk = idx / (COUT / 4);
            int cq = idx % (COUT / 4);
            *(float4*)&sW[kk][cq * 4] = ((const float4*)(W + (size_t)(k0 + kk) * COUT))[cq];
        }
        __syncthreads();

        #pragma unroll 4
        for (int kk = 0; kk < KC; kk++) {
            ulonglong2 w01 = *(const ulonglong2*)&sW[kk][tx * TC];
            ulonglong2 w23 = *(const ulonglong2*)&sW[kk][tx * TC + 4];
            #pragma unroll
            for (int j = 0; j < TR; j++) {
                float xv = sX[r0 + j][kk];
                unsigned long long xx = pack2(xv, xv);
                ffma2(acc[j][0], xx, w01.x);
                ffma2(acc[j][1], xx, w01.y);
                ffma2(acc[j][2], xx, w23.x);
                ffma2(acc[j][3], xx, w23.y);
            }
        }
        __syncthreads();
    }

    #pragma unroll
    for (int j = 0; j < TR; j++) {
        int grow = r0base + r0 + j;
        if (grow < nrows) {
            float2 p0 = unpack2(acc[j][0]);
            float2 p1 = unpack2(acc[j][1]);
            float2 p2 = unpack2(acc[j][2]);
            float2 p3 = unpack2(acc[j][3]);
            float4* yp = (float4*)(Y + (size_t)grow * COUT + tx * TC);
            yp[0] = make_float4(p0.x, p0.y, p1.x, p1.y);
            yp[1] = make_float4(p2.x, p2.y, p3.x, p3.y);
        }
    }
}

// ---------------- layer-1 aggregation: warp per dst, smem-staged records ----------------
__global__ __launch_bounds__(256)
void k_agg1(const float* __restrict__ xw, const float* __restrict__ b,
            const float* __restrict__ a, float* __restrict__ outbuf) {
    __shared__ int2 srec[8][32];
    int wq   = threadIdx.x >> 5;
    int lane = threadIdx.x & 31;
    int dst  = blockIdx.x * 8 + wq;
    if (dst >= NN) return;

    const float4* xw4 = (const float4*)xw;
    float dv = g_dinv1[dst];
    float4 acc = xw4[(size_t)dst * 32 + lane];
    float sc = dv * dv;
    acc.x *= sc; acc.y *= sc; acc.z *= sc; acc.w *= sc;

    int start = g_rowptr[dst], end = g_rowptr[dst + 1];
    for (int base = start; base < end; base += 32) {
        int n = end - base; if (n > 32) n = 32;
        if (lane < n) srec[wq][lane] = g_e1[base + lane];
        __syncwarp();
        int j = 0;
        for (; j + 4 <= n; j += 4) {
            int2 r0 = srec[wq][j], r1 = srec[wq][j + 1];
            int2 r2 = srec[wq][j + 2], r3 = srec[wq][j + 3];
            float4 v0 = xw4[(size_t)r0.x * 32 + lane];
            float4 v1 = xw4[(size_t)r1.x * 32 + lane];
            float4 v2 = xw4[(size_t)r2.x * 32 + lane];
            float4 v3 = xw4[(size_t)r3.x * 32 + lane];
            float c0 = __int_as_float(r0.y), c1 = __int_as_float(r1.y);
            float c2 = __int_as_float(r2.y), c3 = __int_as_float(r3.y);
            acc.x += c0 * v0.x; acc.y += c0 * v0.y; acc.z += c0 * v0.z; acc.w += c0 * v0.w;
            acc.x += c1 * v1.x; acc.y += c1 * v1.y; acc.z += c1 * v1.z; acc.w += c1 * v1.w;
            acc.x += c2 * v2.x; acc.y += c2 * v2.y; acc.z += c2 * v2.z; acc.w += c2 * v2.w;
            acc.x += c3 * v3.x; acc.y += c3 * v3.y; acc.z += c3 * v3.z; acc.w += c3 * v3.w;
        }
        for (; j < n; j++) {
            int2 r = srec[wq][j];
            float c = __int_as_float(r.y);
            float4 v = xw4[(size_t)r.x * 32 + lane];
            acc.x += c * v.x; acc.y += c * v.y; acc.z += c * v.z; acc.w += c * v.w;
        }
        __syncwarp();
    }

    float4 bb = ((const float4*)b)[lane];
    float4 aa = ((const float4*)a)[lane];
    acc.x += bb.x; acc.y += bb.y; acc.z += bb.z; acc.w += bb.w;
    acc.x = (acc.x >= 0.f) ? acc.x : aa.x * acc.x;
    acc.y = (acc.y >= 0.f) ? acc.y : aa.y * acc.y;
    acc.z = (acc.z >= 0.f) ? acc.z : aa.z * acc.z;
    acc.w = (acc.w >= 0.f) ? acc.w : aa.w * acc.w;
    ((float4*)outbuf)[(size_t)dst * 32 + lane] = acc;
}

// ---------------- layer-2 aggregation: warp per dst, lane owns float2 (64 ch) ----------------
__global__ __launch_bounds__(256)
void k_agg2(const float* __restrict__ xw, const float* __restrict__ b,
            const float* __restrict__ a, float* __restrict__ outbuf) {
    __shared__ int2 srec[8][32];
    int wq   = threadIdx.x >> 5;
    int lane = threadIdx.x & 31;
    int dst  = blockIdx.x * 8 + wq;
    if (dst >= NN) return;

    const float2* xw2 = (const float2*)xw;
    float dv = g_dinv2[dst];
    float2 acc = xw2[(size_t)dst * 32 + lane];
    float sc = dv * dv;
    acc.x *= sc; acc.y *= sc;

    int start = g_rowptr[dst], end = g_rowptr[dst + 1];
    for (int base = start; base < end; base += 32) {
        int n = end - base; if (n > 32) n = 32;
        if (lane < n) srec[wq][lane] = g_e2[base + lane];
        __syncwarp();
        int j = 0;
        for (; j + 4 <= n; j += 4) {
            int2 r0 = srec[wq][j], r1 = srec[wq][j + 1];
            int2 r2 = srec[wq][j + 2], r3 = srec[wq][j + 3];
            float c0 = __int_as_float(r0.y), c1 = __int_as_float(r1.y);
            float c2 = __int_as_float(r2.y), c3 = __int_as_float(r3.y);
            if (c0 != 0.f) { float2 v = xw2[(size_t)r0.x * 32 + lane]; acc.x += c0 * v.x; acc.y += c0 * v.y; }
            if (c1 != 0.f) { float2 v = xw2[(size_t)r1.x * 32 + lane]; acc.x += c1 * v.x; acc.y += c1 * v.y; }
            if (c2 != 0.f) { float2 v = xw2[(size_t)r2.x * 32 + lane]; acc.x += c2 * v.x; acc.y += c2 * v.y; }
            if (c3 != 0.f) { float2 v = xw2[(size_t)r3.x * 32 + lane]; acc.x += c3 * v.x; acc.y += c3 * v.y; }
        }
        for (; j < n; j++) {
            int2 r = srec[wq][j];
            float c = __int_as_float(r.y);
            if (c != 0.f) { float2 v = xw2[(size_t)r.x * 32 + lane]; acc.x += c * v.x; acc.y += c * v.y; }
        }
        __syncwarp();
    }

    float2 bb = ((const float2*)b)[lane];
    float2 aa = ((const float2*)a)[lane];
    acc.x += bb.x; acc.y += bb.y;
    acc.x = (acc.x >= 0.f) ? acc.x : aa.x * acc.x;
    acc.y = (acc.y >= 0.f) ? acc.y : aa.y * acc.y;
    ((float2*)outbuf)[(size_t)dst * 32 + lane] = acc;
}

// ---------------- final: half-split average ----------------
__global__ __launch_bounds__(256)
void k_final(const float* __restrict__ buf, float* __restrict__ out) {
    int i = blockIdx.x * 256 + threadIdx.x;          // float4 index
    if (i >= HALF * (CH2 / 4)) return;
    float4 v1 = ((const float4*)buf)[i];
    float4 v2 = ((const float4*)buf)[i + (size_t)HALF * (CH2 / 4)];
    float4 o = make_float4(0.5f * (v1.x + v2.x), 0.5f * (v1.y + v2.y),
                           0.5f * (v1.z + v2.z), 0.5f * (v1.w + v2.w));
    ((float4*)out)[i] = o;
}

// ---------------- launch ----------------
extern "C" void kernel_launch(void* const* d_in, const int* in_sizes, int n_in,
                              void* d_out, int out_size) {
    const float* x   = (const float*)d_in[0];
    const int*   ei  = (const int*)d_in[1];    // int32 (JAX x64 disabled)
    const float* ew  = (const float*)d_in[2];
    const int*   et  = (const int*)d_in[3];    // int32
    const float* W1  = (const float*)d_in[4];
    const float* b1  = (const float*)d_in[5];
    const float* a1  = (const float*)d_in[6];
    const float* W2  = (const float*)d_in[7];
    const float* b2  = (const float*)d_in[8];
    const float* a2  = (const float*)d_in[9];
    float* out = (float*)d_out;

    // lazy one-time host resource creation (CUDA is initialized by now; the
    // GPU work below is identical on every call)
    if (!g_s2) {
        cudaStreamCreateWithFlags(&g_s2, cudaStreamNonBlocking);
        cudaEventCreateWithFlags(&g_evFork, cudaEventDisableTiming);
        cudaEventCreateWithFlags(&g_evJoin, cudaEventDisableTiming);
    }

    float *xw1, *buf1, *xw2, *buf2;
    cudaGetSymbolAddress((void**)&xw1,  g_xw1);
    cudaGetSymbolAddress((void**)&buf1, g_buf1);
    cudaGetSymbolAddress((void**)&xw2,  g_xw2);
    cudaGetSymbolAddress((void**)&buf2, g_buf2);

    const int nodeGrid = (NN + 255) / 256;
    const int edgeGrid = (NE + 255) / 256;
    const int aggGrid  = (NN + 7) / 8;            // 8 warps per 256-thread block

    // ---- fork: GEMM1 on side stream, concurrent with the CSR build ----
    cudaEventRecord(g_evFork, 0);
    cudaStreamWaitEvent(g_s2, g_evFork, 0);
    k_gemm<CH1><<<(NN + 127) / 128, 256, 0, g_s2>>>(x, W1, xw1, NN);
    cudaEventRecord(g_evJoin, g_s2);

    // ---- CSR build + norm coefficients (default stream) ----
    k_init<<<nodeGrid, 256>>>();
    k_pass1<<<edgeGrid, 256>>>(ei, ew, et);
    k_scan1<<<NB1, 256>>>();
    k_scan2<<<1, 512>>>();
    k_scan3<<<NB1, 256>>>();
    k_reorder<<<edgeGrid, 256>>>(ei, ew, et);

    // ---- join: agg1 needs both xw1 (side stream) and CSR (default) ----
    cudaStreamWaitEvent(0, g_evJoin, 0);
    k_agg1<<<aggGrid, 256>>>(xw1, b1, a1, buf1);

    // layer 2  (tile rows = 256 for COUT=64)
    k_gemm<CH2><<<(NN + 255) / 256, 256>>>(buf1, W2, xw2, NN);
    k_agg2<<<aggGrid, 256>>>(xw2, b2, a2, buf2);

    // epilogue
    k_final<<<(HALF * (CH2 / 4) + 255) / 256, 256>>>(buf2, out);
}

// round 13
// speedup vs baseline: 1.9844x; 1.0998x over previous
#include <cuda_runtime.h>
#include <cstdint>

#define NN   100000
#define NE   1600000
#define CIN  128
#define CH1  128
#define CH2  64
#define HALF (NN/2)
#define NB1  ((NN + 255) / 256)     // 391 scan blocks

// ---------------- scratch (static device globals; no allocs) ----------------
__device__ __align__(16) float g_xw1[(size_t)NN * CH1];   // x @ W1
__device__ __align__(16) float g_buf1[(size_t)NN * CH1];  // h1 = prelu(agg1)
__device__ __align__(16) float g_xw2[(size_t)NN * CH2];   // h1 @ W2
__device__ float        g_dinv1[NN];
__device__ float        g_dinv2[NN];
__device__ unsigned int g_pk[NN];           // packed: cnt (low 16) | et_sum (high 16)
__device__ float        g_wsum[NN];         // sum of edge weights per dst
__device__ int   g_rowptr[NN + 1];          // CSR row pointers
__device__ int   g_cursor[NN];              // fill cursors for reorder
__device__ int   g_psum[NB1];               // block partial sums for scan
__device__ __align__(16) int4 g_rec[NE];    // {src, c1_bits, c2_bits, 0} sorted by dst

// ---------------- side stream + events: lazily created on first call ----------
static cudaStream_t g_s2     = nullptr;
static cudaEvent_t  g_evFork = nullptr;
static cudaEvent_t  g_evJoin = nullptr;

// ---------------- f32x2 packed math helpers ----------------
__device__ __forceinline__ unsigned long long pack2(float x, float y) {
    unsigned long long r;
    asm("mov.b64 %0, {%1, %2};" : "=l"(r) : "f"(x), "f"(y));
    return r;
}
__device__ __forceinline__ void ffma2(unsigned long long& d,
                                      unsigned long long a, unsigned long long b) {
    asm("fma.rn.f32x2 %0, %1, %2, %3;" : "=l"(d) : "l"(a), "l"(b), "l"(d));
}
__device__ __forceinline__ float2 unpack2(unsigned long long v) {
    float2 f;
    asm("mov.b64 {%0, %1}, %2;" : "=f"(f.x), "=f"(f.y) : "l"(v));
    return f;
}

// ---------------- prep: init / histogram ----------------
__global__ __launch_bounds__(256) void k_init() {
    int i = blockIdx.x * 256 + threadIdx.x;
    if (i < NN) { g_pk[i] = 0u; g_wsum[i] = 0.f; }
}

__global__ __launch_bounds__(256) void k_pass1(const int* __restrict__ ei,
                                               const float* __restrict__ w,
                                               const int* __restrict__ et) {
    int e = blockIdx.x * 256 + threadIdx.x;
    if (e >= NE) return;
    int d = ei[NE + e];
    atomicAdd(&g_pk[d], 1u | ((unsigned)et[e] << 16));
    atomicAdd(&g_wsum[d], w[e]);
}

// ---------------- 3-kernel exclusive scan of counts -> g_rowptr ----------------
__global__ __launch_bounds__(256) void k_scan1() {
    __shared__ int s[256];
    int tid = threadIdx.x;
    int i = blockIdx.x * 256 + tid;
    int v = (i < NN) ? (int)(g_pk[i] & 0xFFFFu) : 0;
    s[tid] = v;
    __syncthreads();
    for (int off = 1; off < 256; off <<= 1) {
        int t = (tid >= off) ? s[tid - off] : 0;
        __syncthreads();
        s[tid] += t;
        __syncthreads();
    }
    if (i < NN) g_rowptr[i] = s[tid] - v;   // block-local exclusive
    if (tid == 255) g_psum[blockIdx.x] = s[255];
}

__global__ __launch_bounds__(512) void k_scan2() {
    __shared__ int s[512];
    int tid = threadIdx.x;
    int v = (tid < NB1) ? g_psum[tid] : 0;
    s[tid] = v;
    __syncthreads();
    for (int off = 1; off < 512; off <<= 1) {
        int t = (tid >= off) ? s[tid - off] : 0;
        __syncthreads();
        s[tid] += t;
        __syncthreads();
    }
    if (tid < NB1) g_psum[tid] = s[tid] - v;   // exclusive over blocks
}

__global__ __launch_bounds__(256) void k_scan3() {      // + fused rsqrt of degrees
    int i = blockIdx.x * 256 + threadIdx.x;
    if (i < NN) {
        int r = g_rowptr[i] + g_psum[blockIdx.x];
        g_rowptr[i] = r;
        g_cursor[i] = r;
        g_dinv1[i] = rsqrtf(g_wsum[i] + 1.0f);                    // + self loop
        g_dinv2[i] = rsqrtf((float)(g_pk[i] >> 16) + 1.0f);
    }
    if (i == 0) g_rowptr[NN] = NE;
}

// ---------------- reorder edges into dst-sorted records (one STG.128) --------
__global__ __launch_bounds__(256) void k_reorder(const int* __restrict__ ei,
                                                 const float* __restrict__ w,
                                                 const int* __restrict__ et) {
    int e = blockIdx.x * 256 + threadIdx.x;
    if (e >= NE) return;
    int s = ei[e];
    int d = ei[NE + e];
    int pos = atomicAdd(&g_cursor[d], 1);
    float c1 = g_dinv1[s] * w[e] * g_dinv1[d];
    float c2 = g_dinv2[s] * (float)et[e] * g_dinv2[d];
    g_rec[pos] = make_int4(s, __float_as_int(c1), __float_as_int(c2), 0);
}

// ---------------- GEMM: Y[nrows,COUT] = X[nrows,CIN] @ W[CIN,COUT] ----------------
template<int COUT>
__global__ __launch_bounds__(256)
void k_gemm(const float* __restrict__ X, const float* __restrict__ W,
            float* __restrict__ Y, int nrows) {
    constexpr int TC = 8, TR = 8, KC = 32;
    constexpr int CG = COUT / TC;
    constexpr int RG = 256 / CG;
    constexpr int RT = RG * TR;
    __shared__ float sX[RT][KC];
    __shared__ float sW[KC][COUT];

    int tid = threadIdx.x;
    int tx = tid % CG, ty = tid / CG;
    int r0base = blockIdx.x * RT;
    int r0 = ty * TR;

    unsigned long long acc[TR][4];
    #pragma unroll
    for (int j = 0; j < TR; j++) {
        acc[j][0] = 0ULL; acc[j][1] = 0ULL; acc[j][2] = 0ULL; acc[j][3] = 0ULL;
    }

    for (int k0 = 0; k0 < CIN; k0 += KC) {
        #pragma unroll
        for (int idx = tid; idx < RT * (KC / 4); idx += 256) {
            int row = idx / (KC / 4);
            int kq  = idx % (KC / 4);
            int grow = r0base + row;
            float4 v = (grow < nrows)
                ? ((const float4*)(X + (size_t)grow * CIN + k0))[kq]
                : make_float4(0.f, 0.f, 0.f, 0.f);
            *(float4*)&sX[row][kq * 4] = v;
        }
        #pragma unroll
        for (int idx = tid; idx < KC * (COUT / 4); idx += 256) {
            int kk = idx / (COUT / 4);
            int cq = idx % (COUT / 4);
            *(float4*)&sW[kk][cq * 4] = ((const float4*)(W + (size_t)(k0 + kk) * COUT))[cq];
        }
        __syncthreads();

        #pragma unroll 4
        for (int kk = 0; kk < KC; kk++) {
            ulonglong2 w01 = *(const ulonglong2*)&sW[kk][tx * TC];
            ulonglong2 w23 = *(const ulonglong2*)&sW[kk][tx * TC + 4];
            #pragma unroll
            for (int j = 0; j < TR; j++) {
                float xv = sX[r0 + j][kk];
                unsigned long long xx = pack2(xv, xv);
                ffma2(acc[j][0], xx, w01.x);
                ffma2(acc[j][1], xx, w01.y);
                ffma2(acc[j][2], xx, w23.x);
                ffma2(acc[j][3], xx, w23.y);
            }
        }
        __syncthreads();
    }

    #pragma unroll
    for (int j = 0; j < TR; j++) {
        int grow = r0base + r0 + j;
        if (grow < nrows) {
            float2 p0 = unpack2(acc[j][0]);
            float2 p1 = unpack2(acc[j][1]);
            float2 p2 = unpack2(acc[j][2]);
            float2 p3 = unpack2(acc[j][3]);
            float4* yp = (float4*)(Y + (size_t)grow * COUT + tx * TC);
            yp[0] = make_float4(p0.x, p0.y, p1.x, p1.y);
            yp[1] = make_float4(p2.x, p2.y, p3.x, p3.y);
        }
    }
}

// ---------------- layer-1 aggregation: warp per dst, smem-staged records ----------------
__global__ __launch_bounds__(256)
void k_agg1(const float* __restrict__ xw, const float* __restrict__ b,
            const float* __restrict__ a, float* __restrict__ outbuf) {
    __shared__ int4 srec[8][32];
    int wq   = threadIdx.x >> 5;
    int lane = threadIdx.x & 31;
    int dst  = blockIdx.x * 8 + wq;
    if (dst >= NN) return;

    const float4* xw4 = (const float4*)xw;
    float dv = g_dinv1[dst];
    float4 acc = xw4[(size_t)dst * 32 + lane];
    float sc = dv * dv;
    acc.x *= sc; acc.y *= sc; acc.z *= sc; acc.w *= sc;

    int start = g_rowptr[dst], end = g_rowptr[dst + 1];
    for (int base = start; base < end; base += 32) {
        int n = end - base; if (n > 32) n = 32;
        if (lane < n) srec[wq][lane] = g_rec[base + lane];
        __syncwarp();
        int j = 0;
        for (; j + 4 <= n; j += 4) {
            int4 r0 = srec[wq][j], r1 = srec[wq][j + 1];
            int4 r2 = srec[wq][j + 2], r3 = srec[wq][j + 3];
            float4 v0 = xw4[(size_t)r0.x * 32 + lane];
            float4 v1 = xw4[(size_t)r1.x * 32 + lane];
            float4 v2 = xw4[(size_t)r2.x * 32 + lane];
            float4 v3 = xw4[(size_t)r3.x * 32 + lane];
            float c0 = __int_as_float(r0.y), c1 = __int_as_float(r1.y);
            float c2 = __int_as_float(r2.y), c3 = __int_as_float(r3.y);
            acc.x += c0 * v0.x; acc.y += c0 * v0.y; acc.z += c0 * v0.z; acc.w += c0 * v0.w;
            acc.x += c1 * v1.x; acc.y += c1 * v1.y; acc.z += c1 * v1.z; acc.w += c1 * v1.w;
            acc.x += c2 * v2.x; acc.y += c2 * v2.y; acc.z += c2 * v2.z; acc.w += c2 * v2.w;
            acc.x += c3 * v3.x; acc.y += c3 * v3.y; acc.z += c3 * v3.z; acc.w += c3 * v3.w;
        }
        for (; j < n; j++) {
            int4 r = srec[wq][j];
            float c = __int_as_float(r.y);
            float4 v = xw4[(size_t)r.x * 32 + lane];
            acc.x += c * v.x; acc.y += c * v.y; acc.z += c * v.z; acc.w += c * v.w;
        }
        __syncwarp();
    }

    float4 bb = ((const float4*)b)[lane];
    float4 aa = ((const float4*)a)[lane];
    acc.x += bb.x; acc.y += bb.y; acc.z += bb.z; acc.w += bb.w;
    acc.x = (acc.x >= 0.f) ? acc.x : aa.x * acc.x;
    acc.y = (acc.y >= 0.f) ? acc.y : aa.y * acc.y;
    acc.z = (acc.z >= 0.f) ? acc.z : aa.z * acc.z;
    acc.w = (acc.w >= 0.f) ? acc.w : aa.w * acc.w;
    ((float4*)outbuf)[(size_t)dst * 32 + lane] = acc;
}

// ---------------- layer-2 aggregation fused with epilogue ----------------
// warp handles node pair (i, i+HALF); writes averaged output directly.
__device__ __forceinline__ float2 agg2_node(const float2* __restrict__ xw2,
                                            int4 (*srec)[32], int wq, int lane,
                                            int dst) {
    float dv = g_dinv2[dst];
    float2 acc = xw2[(size_t)dst * 32 + lane];
    float sc = dv * dv;
    acc.x *= sc; acc.y *= sc;

    int start = g_rowptr[dst], end = g_rowptr[dst + 1];
    for (int base = start; base < end; base += 32) {
        int n = end - base; if (n > 32) n = 32;
        if (lane < n) srec[wq][lane] = g_rec[base + lane];
        __syncwarp();
        int j = 0;
        for (; j + 4 <= n; j += 4) {
            int4 r0 = srec[wq][j], r1 = srec[wq][j + 1];
            int4 r2 = srec[wq][j + 2], r3 = srec[wq][j + 3];
            float c0 = __int_as_float(r0.z), c1 = __int_as_float(r1.z);
            float c2 = __int_as_float(r2.z), c3 = __int_as_float(r3.z);
            if (c0 != 0.f) { float2 v = xw2[(size_t)r0.x * 32 + lane]; acc.x += c0 * v.x; acc.y += c0 * v.y; }
            if (c1 != 0.f) { float2 v = xw2[(size_t)r1.x * 32 + lane]; acc.x += c1 * v.x; acc.y += c1 * v.y; }
            if (c2 != 0.f) { float2 v = xw2[(size_t)r2.x * 32 + lane]; acc.x += c2 * v.x; acc.y += c2 * v.y; }
            if (c3 != 0.f) { float2 v = xw2[(size_t)r3.x * 32 + lane]; acc.x += c3 * v.x; acc.y += c3 * v.y; }
        }
        for (; j < n; j++) {
            int4 r = srec[wq][j];
            float c = __int_as_float(r.z);
            if (c != 0.f) { float2 v = xw2[(size_t)r.x * 32 + lane]; acc.x += c * v.x; acc.y += c * v.y; }
        }
        __syncwarp();
    }
    return acc;
}

__global__ __launch_bounds__(256)
void k_agg2f(const float* __restrict__ xw, const float* __restrict__ b,
             const float* __restrict__ a, float* __restrict__ out) {
    __shared__ int4 srec[8][32];
    int wq   = threadIdx.x >> 5;
    int lane = threadIdx.x & 31;
    int node = blockIdx.x * 8 + wq;
    if (node >= HALF) return;

    const float2* xw2 = (const float2*)xw;
    float2 r1 = agg2_node(xw2, srec, wq, lane, node);
    float2 r2 = agg2_node(xw2, srec, wq, lane, node + HALF);

    float2 bb = ((const float2*)b)[lane];
    float2 aa = ((const float2*)a)[lane];
    r1.x += bb.x; r1.y += bb.y;
    r2.x += bb.x; r2.y += bb.y;
    r1.x = (r1.x >= 0.f) ? r1.x : aa.x * r1.x;
    r1.y = (r1.y >= 0.f) ? r1.y : aa.y * r1.y;
    r2.x = (r2.x >= 0.f) ? r2.x : aa.x * r2.x;
    r2.y = (r2.y >= 0.f) ? r2.y : aa.y * r2.y;
    float2 o = make_float2(0.5f * (r1.x + r2.x), 0.5f * (r1.y + r2.y));
    ((float2*)out)[(size_t)node * 32 + lane] = o;
}

// ---------------- launch ----------------
extern "C" void kernel_launch(void* const* d_in, const int* in_sizes, int n_in,
                              void* d_out, int out_size) {
    const float* x   = (const float*)d_in[0];
    const int*   ei  = (const int*)d_in[1];    // int32 (JAX x64 disabled)
    const float* ew  = (const float*)d_in[2];
    const int*   et  = (const int*)d_in[3];    // int32
    const float* W1  = (const float*)d_in[4];
    const float* b1  = (const float*)d_in[5];
    const float* a1  = (const float*)d_in[6];
    const float* W2  = (const float*)d_in[7];
    const float* b2  = (const float*)d_in[8];
    const float* a2  = (const float*)d_in[9];
    float* out = (float*)d_out;

    if (!g_s2) {
        cudaStreamCreateWithFlags(&g_s2, cudaStreamNonBlocking);
        cudaEventCreateWithFlags(&g_evFork, cudaEventDisableTiming);
        cudaEventCreateWithFlags(&g_evJoin, cudaEventDisableTiming);
    }

    float *xw1, *buf1, *xw2;
    cudaGetSymbolAddress((void**)&xw1,  g_xw1);
    cudaGetSymbolAddress((void**)&buf1, g_buf1);
    cudaGetSymbolAddress((void**)&xw2,  g_xw2);

    const int nodeGrid = (NN + 255) / 256;
    const int edgeGrid = (NE + 255) / 256;
    const int aggGrid  = (NN + 7) / 8;
    const int agg2Grid = (HALF + 7) / 8;

    // ---- fork: GEMM1 on side stream, concurrent with the CSR build ----
    cudaEventRecord(g_evFork, 0);
    cudaStreamWaitEvent(g_s2, g_evFork, 0);
    k_gemm<CH1><<<(NN + 127) / 128, 256, 0, g_s2>>>(x, W1, xw1, NN);
    cudaEventRecord(g_evJoin, g_s2);

    // ---- CSR build + norm coefficients (default stream) ----
    k_init<<<nodeGrid, 256>>>();
    k_pass1<<<edgeGrid, 256>>>(ei, ew, et);
    k_scan1<<<NB1, 256>>>();
    k_scan2<<<1, 512>>>();
    k_scan3<<<NB1, 256>>>();
    k_reorder<<<edgeGrid, 256>>>(ei, ew, et);

    // ---- join: agg1 needs both xw1 (side stream) and CSR (default) ----
    cudaStreamWaitEvent(0, g_evJoin, 0);
    k_agg1<<<aggGrid, 256>>>(xw1, b1, a1, buf1);

    // layer 2
    k_gemm<CH2><<<(NN + 255) / 256, 256>>>(buf1, W2, xw2, NN);
    k_agg2f<<<agg2Grid, 256>>>(xw2, b2, a2, out);
}